// round 12
// baseline (speedup 1.0000x reference)
#include <cuda_runtime.h>
#include <math.h>

#define C 1000          // NUM_CLASSES
#define B 1024          // BATCH
#define TPB 256
#define EPS 1e-4f
#define BETA 0.7f
#define LAMBDA1 3.0f

#define N_TGT 200000000ull              // NUM_EXAMP * NUM_CLASSES
#define GRID  912                       // 152 SMs * 6 resident blocks -> 1 wave
#define GSZ   256                       // out floats per copy group (32 lanes * 8)
#define CHUNK 16                        // groups per ticket (16 KB)
#define ROW_BLOCKS 256                  // blocks doing row work (4 rows each)

// Self-cleaning device state: zero at module load; the last finishing block
// resets everything to zero, so every graph replay sees identical state.
__device__ unsigned long long g_ticket = 0;   // dynamic copy-work counter
__device__ float              g_loss   = 0.0f;// loss accumulator
__device__ unsigned int       g_done   = 0;   // finished-block counter

// ---- block reduction helpers -------------------------------------------------
__device__ __forceinline__ float block_reduce_sum(float val) {
    __shared__ float sh[8];
    __shared__ float res;
    __syncthreads();
    int lane = threadIdx.x & 31;
    int wid  = threadIdx.x >> 5;
    #pragma unroll
    for (int o = 16; o > 0; o >>= 1) val += __shfl_xor_sync(0xffffffffu, val, o);
    if (lane == 0) sh[wid] = val;
    __syncthreads();
    if (wid == 0) {
        float v = (lane < (TPB >> 5)) ? sh[lane] : 0.0f;
        #pragma unroll
        for (int o = 4; o > 0; o >>= 1) v += __shfl_xor_sync(0xffu, v, o);
        if (lane == 0) res = v;
    }
    __syncthreads();
    return res;
}

__device__ __forceinline__ float block_reduce_max(float val) {
    __shared__ float sh[8];
    __shared__ float res;
    __syncthreads();
    int lane = threadIdx.x & 31;
    int wid  = threadIdx.x >> 5;
    #pragma unroll
    for (int o = 16; o > 0; o >>= 1)
        val = fmaxf(val, __shfl_xor_sync(0xffffffffu, val, o));
    if (lane == 0) sh[wid] = val;
    __syncthreads();
    if (wid == 0) {
        float v = (lane < (TPB >> 5)) ? sh[lane] : -INFINITY;
        #pragma unroll
        for (int o = 4; o > 0; o >>= 1)
            v = fmaxf(v, __shfl_xor_sync(0xffu, v, o));
        if (lane == 0) res = v;
    }
    __syncthreads();
    return res;
}

// ---- per-row softmax/EMA/loss ------------------------------------------------
__device__ void row_work(int r,
                         const float* __restrict__ output,
                         const float* __restrict__ target,
                         const int*   __restrict__ label,
                         int start,
                         float*       __restrict__ out)
{
    const int t = threadIdx.x;
    const float* orow = output + (size_t)r * C;

    float v[4];
    #pragma unroll
    for (int i = 0; i < 4; i++) {
        int c = t + i * TPB;
        v[i] = (c < C) ? orow[c] : -INFINITY;
    }

    float m = fmaxf(fmaxf(v[0], v[1]), fmaxf(v[2], v[3]));
    m = block_reduce_max(m);

    float e[4];
    float s = 0.0f;
    #pragma unroll
    for (int i = 0; i < 4; i++) {
        int c = t + i * TPB;
        e[i] = (c < C) ? expf(v[i] - m) : 0.0f;
        s += e[i];
    }
    const float S = block_reduce_sum(s);
    const float inv_S = 1.0f / S;
    const float lse = m + logf(S);

    float yp[4];
    float cs = 0.0f;
    #pragma unroll
    for (int i = 0; i < 4; i++) {
        int c = t + i * TPB;
        if (c < C) {
            yp[i] = fminf(fmaxf(e[i] * inv_S, EPS), 1.0f - EPS);
            cs += yp[i];
        } else {
            yp[i] = 0.0f;
        }
    }
    const float inv_cs = 1.0f / block_reduce_sum(cs);

    const float* trow = target + (size_t)(start + r) * C;
    float* outrow = out + 1 + (size_t)(start + r) * C;

    float dot = 0.0f;
    #pragma unroll
    for (int i = 0; i < 4; i++) {
        int c = t + i * TPB;
        if (c < C) {
            float nt = BETA * trow[c] + (1.0f - BETA) * (yp[i] * inv_cs);
            outrow[c] = nt;
            dot += nt * yp[i];
        }
    }
    const float D = block_reduce_sum(dot);

    if (t == 0) {
        const int l = label[r];
        const float ce  = -(orow[l] - lse);
        const float elr = logf(1.0f - D);
        atomicAdd(&g_loss, (ce + LAMBDA1 * elr) * (1.0f / (float)B));
    }
}

// ---- bulk copy: out[i] = tgt[i-1] for i in [1, N_TGT], skipping EMA slice ----
// Group g owns OUT floats [256g, 256g+256): stores 128B line-aligned, one
// writer per line; loads shifted -1 float (overlap absorbed by L2).
__device__ void copy_work(const float* __restrict__ tgt,
                          size_t G0, size_t s_beg, size_t s_end,
                          float* __restrict__ out)
{
    const size_t NG   = N_TGT / GSZ + 1;          // 781,251 (last group = tail)
    const int    lane = threadIdx.x & 31;

    for (;;) {
        unsigned long long t;
        if (lane == 0) t = atomicAdd(&g_ticket, 1ULL);
        t = __shfl_sync(0xffffffffu, t, 0);
        const size_t gbase = (size_t)t * CHUNK;
        if (gbase >= NG) break;

        #pragma unroll 1
        for (int k = 0; k < CHUNK; k++) {
            const size_t g = gbase + k;
            if (g >= NG) break;
            if (g > G0 && g < G0 + 4000) continue;          // slice interior

            const bool partial = (g == 0) | (g + 1 == NG) |
                                 (g == G0) | (g == G0 + 4000);
            if (!partial) {
                const float* src = tgt + g * GSZ - 1 + lane;   // shifted loads
                float a[8];
                #pragma unroll
                for (int j = 0; j < 8; j++) a[j] = __ldcs(src + 32 * j);

                float* dst = out + g * GSZ + lane;             // aligned stores
                #pragma unroll
                for (int j = 0; j < 8; j++) __stcs(dst + 32 * j, a[j]);
            } else {
                #pragma unroll
                for (int j = 0; j < 8; j++) {
                    const size_t i = g * GSZ + lane + 32 * j;
                    if (i >= 1 && i <= N_TGT && (i < s_beg || i >= s_end))
                        out[i] = __ldcs(tgt + i - 1);
                }
            }
        }
    }
}

__global__ void __launch_bounds__(TPB, 6)
elr_fused_kernel(const float* __restrict__ output,
                 const float* __restrict__ target,
                 const int*   __restrict__ label,
                 const int*   __restrict__ index,
                 float*       __restrict__ out)
{
    const int start = (*index) * B;

    // row phase: only blocks 0..255 (4 rows each); rest start copying at t=0
    if (blockIdx.x < ROW_BLOCKS) {
        #pragma unroll
        for (int k = 0; k < 4; k++)
            row_work(blockIdx.x + ROW_BLOCKS * k, output, target, label, start, out);
    }

    // copy phase: ticket-scheduled across all warps
    const size_t s_beg = 1 + (size_t)start * C;          // slice in OUT indices
    const size_t s_end = s_beg + (size_t)B * C;
    const size_t G0    = (size_t)start * C / GSZ;        // = 4000 * index
    copy_work(target, G0, s_beg, s_end, out);

    // completion protocol: last block publishes the loss and resets all state
    __syncthreads();
    if (threadIdx.x == 0) {
        __threadfence();
        const unsigned int d = atomicAdd(&g_done, 1u);
        if (d == GRID - 1) {
            out[0] = atomicExch(&g_loss, 0.0f);      // publish + reset loss
            atomicExch(&g_ticket, 0ULL);             // reset work counter
            __threadfence();
            atomicExch(&g_done, 0u);                 // reset arrival counter
        }
    }
}

extern "C" void kernel_launch(void* const* d_in, const int* in_sizes, int n_in,
                              void* d_out, int out_size) {
    const float* output = (const float*)d_in[0];
    const float* target = (const float*)d_in[1];
    const int*   label  = (const int*)  d_in[2];
    const int*   index  = (const int*)  d_in[3];
    float* out = (float*)d_out;

    // single self-cleaning kernel: no memset nodes, 1-node graph
    elr_fused_kernel<<<GRID, TPB, 0, 0>>>(output, target, label, index, out);
}